// round 4
// baseline (speedup 1.0000x reference)
#include <cuda_runtime.h>
#include <math.h>

// Problem constants
#define BB     16
#define JJ     256
#define KK     384
#define CMETA  6
#define CIN    8      // C_MODEL(1) + C_OBS(1) + C_META(6)
#define WD     32
#define DEPTH  3
#define SS     32     // sample_size
#define JK     (JJ*KK)        // 98304
#define NPTS   (BB*JK)        // 1572864

// Scratch (device globals; no allocation allowed)
__device__ int   g_fmt;                 // 0=uint8, 1=int32, 2=float32
__device__ int   g_sel[BB][SS];         // selected j indices per batch (unordered set)
__device__ float g_img_sum[BB][WD];     // masked sum of image-branch hidden
__device__ float g_img_cnt[BB];         // masked count

__device__ __forceinline__ bool mask_at(const void* m, int fmt, int i) {
    if (fmt == 0) return ((const unsigned char*)m)[i] != 0;
    if (fmt == 1) return ((const int*)m)[i] != 0;
    return ((const float*)m)[i] != 0.0f;
}

// ---------------------------------------------------------------------------
// Kernel 0: detect mask storage dtype by bit pattern. Deterministic per input.
// ---------------------------------------------------------------------------
__global__ void k_detect(const unsigned int* mask_w) {
    bool all_int = true, all_flt = true;
    for (int i = 0; i < 256; i++) {
        unsigned int v = mask_w[i];
        all_int = all_int && (v <= 1u);
        all_flt = all_flt && (v == 0u || v == 0x3F800000u);
    }
    g_fmt = all_int ? 1 : (all_flt ? 2 : 0);
}

// ---------------------------------------------------------------------------
// Kernel 1: JAX partitionable threefry gumbel ranking.
// Counter n as u64 via iota_2x32_shape -> inputs (x0 = hi = 0, x1 = lo = n).
// bit_width==32 path returns XOR-FOLD of the two output lanes:
//   bits = out0 ^ out1    (this round's change)
// Selection = top-32 of bits per batch (gumbel chain is monotone in bits),
// ties broken by lower index (lax.top_k stability).
// ---------------------------------------------------------------------------
__device__ __forceinline__ unsigned int rotl32(unsigned int x, int r) {
    return (x << r) | (x >> (32 - r));
}

__global__ void k_select(const void* mask) {
    const int b = blockIdx.x;
    const int j = threadIdx.x;   // 256 threads
    const int fmt = g_fmt;

    // zero accumulators for this replay (graph is replayed many times)
    if (j < WD) g_img_sum[b][j] = 0.0f;
    if (j == 0) g_img_cnt[b] = 0.0f;

    // alive = any(mask[b,j,:])  (P(dead) ~ 2^-384, but keep exact semantics)
    const int base = (b * JJ + j) * KK;
    bool alive = false;
    for (int k = 0; k < KK; k++) {
        if (mask_at(mask, fmt, base + k)) { alive = true; break; }
    }

    // --- threefry2x32-20, key=(0,42), counter n = b*256+j ---
    const unsigned int n = (unsigned int)(b * JJ + j);   // 0..4095
    unsigned int x0 = 0u;      // counter >> 32 == 0
    unsigned int x1 = n;       // low 32 bits of counter
    const unsigned int ks0 = 0u;
    const unsigned int ks1 = 42u;
    const unsigned int ks2 = 0x1BD11BDAu ^ 42u;
    x0 += ks0; x1 += ks1;
#define TF_ROUND(r) { x0 += x1; x1 = rotl32(x1, (r)); x1 ^= x0; }
    TF_ROUND(13) TF_ROUND(15) TF_ROUND(26) TF_ROUND(6)
    x0 += ks1; x1 += ks2 + 1u;
    TF_ROUND(17) TF_ROUND(29) TF_ROUND(16) TF_ROUND(24)
    x0 += ks2; x1 += ks0 + 2u;
    TF_ROUND(13) TF_ROUND(15) TF_ROUND(26) TF_ROUND(6)
    x0 += ks0; x1 += ks1 + 3u;
    TF_ROUND(17) TF_ROUND(29) TF_ROUND(16) TF_ROUND(24)
    x0 += ks1; x1 += ks2 + 4u;
    TF_ROUND(13) TF_ROUND(15) TF_ROUND(26) TF_ROUND(6)
    x0 += ks2; x1 += ks0 + 5u;
#undef TF_ROUND
    const unsigned int bits = x0 ^ x1;   // XOR-fold of both output lanes

    // Rank on the uniform mantissa bits (monotone with the gumbel score).
    const unsigned int keyv = alive ? ((bits >> 9) | 0x80000000u) : 0u;

    __shared__ unsigned int sc[JJ];
    __shared__ int cnt;
    sc[j] = keyv;
    if (j == 0) cnt = 0;
    __syncthreads();

    // rank by (key desc, index asc) — matches lax.top_k stability
    int rank = 0;
    for (int t = 0; t < JJ; t++) {
        unsigned int s = sc[t];
        if (s > keyv || (s == keyv && t < j)) rank++;
    }
    if (rank < SS) {
        int slot = atomicAdd(&cnt, 1);
        g_sel[b][slot] = j;                    // unordered set — order irrelevant (sum)
    }
}

// ---------------------------------------------------------------------------
// Kernel 2: image branch over sampled rows. grid = BB*SS*3 blocks, 128 thr,
// one (b, sel_j, k) point per thread.
// ---------------------------------------------------------------------------
__global__ void __launch_bounds__(128) k_image(
    const float* __restrict__ Imodel, const float* __restrict__ Iobs,
    const float* __restrict__ metadata, const void* __restrict__ mask,
    const float* __restrict__ W_img_in, const float* __restrict__ b_img_in,
    const float* __restrict__ W_img, const float* __restrict__ b_img)
{
    __shared__ __align__(16) float WT0[WD][CIN];        // [c][i] transposed
    __shared__ __align__(16) float WT[DEPTH][WD][WD];   // [d][c][i] transposed
    __shared__ float bs0[WD];
    __shared__ float bsd[DEPTH][WD];

    const int tid = threadIdx.x;
    for (int t = tid; t < CIN * WD; t += 128) { int i = t / WD, c = t % WD; WT0[c][i] = W_img_in[t]; }
    for (int t = tid; t < DEPTH * WD * WD; t += 128) {
        int d = t / (WD * WD); int r = t % (WD * WD); int i = r / WD, c = r % WD;
        WT[d][c][i] = W_img[t];
    }
    for (int t = tid; t < WD; t += 128) bs0[t] = b_img_in[t];
    for (int t = tid; t < DEPTH * WD; t += 128) bsd[t / WD][t % WD] = b_img[t];
    __syncthreads();

    const int blk = blockIdx.x;
    const int chunk = blk % 3;
    const int bs = blk / 3;
    const int b = bs / SS;
    const int s = bs % SS;
    const int j = g_sel[b][s];
    const int fmt = g_fmt;

    const int k = chunk * 128 + tid;          // 0..383, always valid
    const int p = (b * JJ + j) * KK + k;

    float x[CIN];
    x[0] = Imodel[p];
    x[1] = Iobs[p];
    const float* mdp = metadata + (size_t)p * CMETA;
#pragma unroll
    for (int i = 0; i < CMETA; i++) x[2 + i] = mdp[i];

    float h[WD], h2[WD];
#pragma unroll
    for (int c = 0; c < WD; c++) {
        float a = bs0[c];
#pragma unroll
        for (int i = 0; i < CIN; i++) a = fmaf(x[i], WT0[c][i], a);
        h[c] = a;
    }
#pragma unroll 1
    for (int d = 0; d < DEPTH; d++) {
#pragma unroll
        for (int c = 0; c < WD; c++) {
            float a = bsd[d][c];
#pragma unroll
            for (int i = 0; i < WD; i++) a = fmaf(h[i], WT[d][c][i], a);
            h2[c] = fmaxf(a, 0.0f);
        }
#pragma unroll
        for (int c = 0; c < WD; c++) h[c] = h2[c];
    }

    const float m = mask_at(mask, fmt, p) ? 1.0f : 0.0f;

    // warp-reduce masked sums, lane0 atomics to global
#pragma unroll
    for (int c = 0; c < WD; c++) {
        float v = m * h[c];
#pragma unroll
        for (int o = 16; o > 0; o >>= 1) v += __shfl_xor_sync(0xFFFFFFFFu, v, o);
        if ((tid & 31) == 0) atomicAdd(&g_img_sum[b][c], v);
    }
    {
        float v = m;
#pragma unroll
        for (int o = 16; o > 0; o >>= 1) v += __shfl_xor_sync(0xFFFFFFFFu, v, o);
        if ((tid & 31) == 0) atomicAdd(&g_img_cnt[b], v);
    }
}

// ---------------------------------------------------------------------------
// Kernel 3: main branch, 1.57M points, one per thread.
// ---------------------------------------------------------------------------
__global__ void __launch_bounds__(256) k_main(
    const float* __restrict__ metadata, const void* __restrict__ mask,
    const float* __restrict__ W_lin_in, const float* __restrict__ b_lin_in,
    const float* __restrict__ W_mlp, const float* __restrict__ b_mlp,
    const float* __restrict__ W_out, const float* __restrict__ b_out,
    float* __restrict__ out)
{
    __shared__ __align__(16) float WT0[WD][CMETA];      // [c][i]
    __shared__ __align__(16) float WT[DEPTH][WD][WD];   // [d][c][i]
    __shared__ float beff[WD];                          // b_lin + image_rep[b]
    __shared__ float bsd[DEPTH][WD];
    __shared__ float wout[WD];
    __shared__ float bout;

    const int tid = threadIdx.x;
    const int p0 = blockIdx.x * 256;
    const int b = p0 / JK;

    for (int t = tid; t < CMETA * WD; t += 256) { int i = t / WD, c = t % WD; WT0[c][i] = W_lin_in[t]; }
    for (int t = tid; t < DEPTH * WD * WD; t += 256) {
        int d = t / (WD * WD); int r = t % (WD * WD); int i = r / WD, c = r % WD;
        WT[d][c][i] = W_mlp[t];
    }
    if (tid < WD) {
        float cnt = g_img_cnt[b];
        beff[tid] = b_lin_in[tid] + g_img_sum[b][tid] / cnt;
        wout[tid] = W_out[tid];
    }
    for (int t = tid; t < DEPTH * WD; t += 256) bsd[t / WD][t % WD] = b_mlp[t];
    if (tid == 0) bout = b_out[0];
    __syncthreads();

    const int p = p0 + tid;
    const int fmt = g_fmt;

    float x[CMETA];
    const float* mdp = metadata + (size_t)p * CMETA;
#pragma unroll
    for (int i = 0; i < CMETA; i++) x[i] = mdp[i];

    float h[WD], h2[WD];
#pragma unroll
    for (int c = 0; c < WD; c++) {
        float a = beff[c];
#pragma unroll
        for (int i = 0; i < CMETA; i++) a = fmaf(x[i], WT0[c][i], a);
        h[c] = a;
    }
#pragma unroll 1
    for (int d = 0; d < DEPTH; d++) {
#pragma unroll
        for (int c = 0; c < WD; c++) {
            float a = bsd[d][c];
#pragma unroll
            for (int i = 0; i < WD; i++) a = fmaf(h[i], WT[d][c][i], a);
            h2[c] = fmaxf(a, 0.0f);
        }
#pragma unroll
        for (int c = 0; c < WD; c++) h[c] = h2[c];
    }

    float o = bout;
#pragma unroll
    for (int i = 0; i < WD; i++) o = fmaf(h[i], wout[i], o);

    out[p] = mask_at(mask, fmt, p) ? o : 0.0f;
}

// ---------------------------------------------------------------------------
// Launch: detect -> select -> image -> main (default stream, graph-capturable)
// ---------------------------------------------------------------------------
extern "C" void kernel_launch(void* const* d_in, const int* in_sizes, int n_in,
                              void* d_out, int out_size)
{
    const float* Imodel   = (const float*)d_in[0];
    const float* Iobs     = (const float*)d_in[1];
    const float* metadata = (const float*)d_in[2];
    const void*  mask     = d_in[3];
    // d_in[4] = sample_size (always 32)
    const float* W_img_in = (const float*)d_in[5];
    const float* b_img_in = (const float*)d_in[6];
    const float* W_img    = (const float*)d_in[7];
    const float* b_img    = (const float*)d_in[8];
    const float* W_lin_in = (const float*)d_in[9];
    const float* b_lin_in = (const float*)d_in[10];
    const float* W_mlp    = (const float*)d_in[11];
    const float* b_mlp    = (const float*)d_in[12];
    const float* W_out    = (const float*)d_in[13];
    const float* b_out    = (const float*)d_in[14];
    float* out = (float*)d_out;

    k_detect<<<1, 1>>>((const unsigned int*)mask);
    k_select<<<BB, JJ>>>(mask);
    k_image<<<BB * SS * 3, 128>>>(Imodel, Iobs, metadata, mask,
                                  W_img_in, b_img_in, W_img, b_img);
    k_main<<<NPTS / 256, 256>>>(metadata, mask, W_lin_in, b_lin_in,
                                W_mlp, b_mlp, W_out, b_out, out);
}

// round 5
// speedup vs baseline: 1.3737x; 1.3737x over previous
#include <cuda_runtime.h>
#include <math.h>

// Problem constants
#define BB     16
#define JJ     256
#define KK     384
#define CMETA  6
#define CIN    8      // C_MODEL(1) + C_OBS(1) + C_META(6)
#define WD     32
#define DEPTH  3
#define SS     32     // sample_size
#define JK     (JJ*KK)        // 98304
#define NPTS   (BB*JK)        // 1572864
#define TPB    256
#define PPT    2              // points per thread in k_main
#define PTSBLK (TPB*PPT)      // 512 points per block

// Scratch (device globals; no allocation allowed)
__device__ int   g_fmt;                 // 0=uint8, 1=int32, 2=float32
__device__ int   g_sel[BB][SS];         // selected j indices per batch (unordered set)
__device__ float g_img_sum[BB][WD];     // masked sum of image-branch hidden
__device__ float g_img_cnt[BB];         // masked count

__device__ __forceinline__ bool mask_at(const void* m, int fmt, int i) {
    if (fmt == 0) return ((const unsigned char*)m)[i] != 0;
    if (fmt == 1) return ((const int*)m)[i] != 0;
    return ((const float*)m)[i] != 0.0f;
}

// ---------------------------------------------------------------------------
// Kernel 1: mask-dtype detect (parallel, per-block) + alive flag +
// JAX partitionable threefry gumbel ranking (bits = out0 ^ out1).
// ---------------------------------------------------------------------------
__device__ __forceinline__ unsigned int rotl32(unsigned int x, int r) {
    return (x << r) | (x >> (32 - r));
}

__global__ void __launch_bounds__(JJ) k_select(const void* mask) {
    const int b = blockIdx.x;
    const int j = threadIdx.x;   // 256 threads

    // --- in-kernel mask dtype detection (each block redundantly; no dependency) ---
    __shared__ unsigned int red[2];
    __shared__ int s_fmt;
    if (j == 0) { red[0] = 1u; red[1] = 1u; }
    __syncthreads();
    {
        unsigned int v = ((const unsigned int*)mask)[j];
        if (v > 1u) atomicAnd(&red[0], 0u);
        if (!(v == 0u || v == 0x3F800000u)) atomicAnd(&red[1], 0u);
    }
    __syncthreads();
    if (j == 0) {
        int f = red[0] ? 1 : (red[1] ? 2 : 0);
        s_fmt = f;
        if (b == 0) g_fmt = f;       // for downstream kernels
    }
    __syncthreads();
    const int fmt = s_fmt;

    // zero accumulators for this replay (graph is replayed many times)
    if (j < WD) g_img_sum[b][j] = 0.0f;
    if (j == 0) g_img_cnt[b] = 0.0f;

    // alive = any(mask[b,j,:])
    const int base = (b * JJ + j) * KK;
    bool alive = false;
    for (int k = 0; k < KK; k++) {
        if (mask_at(mask, fmt, base + k)) { alive = true; break; }
    }

    // --- threefry2x32-20, key=(0,42), counter n = b*256+j, bits = out0^out1 ---
    const unsigned int n = (unsigned int)(b * JJ + j);
    unsigned int x0 = 0u;
    unsigned int x1 = n;
    const unsigned int ks0 = 0u;
    const unsigned int ks1 = 42u;
    const unsigned int ks2 = 0x1BD11BDAu ^ 42u;
    x0 += ks0; x1 += ks1;
#define TF_ROUND(r) { x0 += x1; x1 = rotl32(x1, (r)); x1 ^= x0; }
    TF_ROUND(13) TF_ROUND(15) TF_ROUND(26) TF_ROUND(6)
    x0 += ks1; x1 += ks2 + 1u;
    TF_ROUND(17) TF_ROUND(29) TF_ROUND(16) TF_ROUND(24)
    x0 += ks2; x1 += ks0 + 2u;
    TF_ROUND(13) TF_ROUND(15) TF_ROUND(26) TF_ROUND(6)
    x0 += ks0; x1 += ks1 + 3u;
    TF_ROUND(17) TF_ROUND(29) TF_ROUND(16) TF_ROUND(24)
    x0 += ks1; x1 += ks2 + 4u;
    TF_ROUND(13) TF_ROUND(15) TF_ROUND(26) TF_ROUND(6)
    x0 += ks2; x1 += ks0 + 5u;
#undef TF_ROUND
    const unsigned int bits = x0 ^ x1;

    // rank on uniform mantissa bits (monotone with the gumbel score)
    const unsigned int keyv = alive ? ((bits >> 9) | 0x80000000u) : 0u;

    __shared__ unsigned int sc[JJ];
    __shared__ int cnt;
    sc[j] = keyv;
    if (j == 0) cnt = 0;
    __syncthreads();

    int rank = 0;
    for (int t = 0; t < JJ; t++) {
        unsigned int s = sc[t];
        if (s > keyv || (s == keyv && t < j)) rank++;
    }
    if (rank < SS) {
        int slot = atomicAdd(&cnt, 1);
        g_sel[b][slot] = j;                    // unordered set — order irrelevant (sum)
    }
}

// ---------------------------------------------------------------------------
// Kernel 2: image branch over sampled rows (small: 512 rows x 384 pts).
// ---------------------------------------------------------------------------
__global__ void __launch_bounds__(128) k_image(
    const float* __restrict__ Imodel, const float* __restrict__ Iobs,
    const float* __restrict__ metadata, const void* __restrict__ mask,
    const float* __restrict__ W_img_in, const float* __restrict__ b_img_in,
    const float* __restrict__ W_img, const float* __restrict__ b_img)
{
    __shared__ __align__(16) float WT0[WD][CIN];        // [c][i] transposed
    __shared__ __align__(16) float WT[DEPTH][WD][WD];   // [d][c][i] transposed
    __shared__ float bs0[WD];
    __shared__ float bsd[DEPTH][WD];

    const int tid = threadIdx.x;
    for (int t = tid; t < CIN * WD; t += 128) { int i = t / WD, c = t % WD; WT0[c][i] = W_img_in[t]; }
    for (int t = tid; t < DEPTH * WD * WD; t += 128) {
        int d = t / (WD * WD); int r = t % (WD * WD); int i = r / WD, c = r % WD;
        WT[d][c][i] = W_img[t];
    }
    for (int t = tid; t < WD; t += 128) bs0[t] = b_img_in[t];
    for (int t = tid; t < DEPTH * WD; t += 128) bsd[t / WD][t % WD] = b_img[t];
    __syncthreads();

    const int blk = blockIdx.x;
    const int chunk = blk % 3;
    const int bs = blk / 3;
    const int b = bs / SS;
    const int s = bs % SS;
    const int j = g_sel[b][s];
    const int fmt = g_fmt;

    const int k = chunk * 128 + tid;          // 0..383
    const int p = (b * JJ + j) * KK + k;

    float x[CIN];
    x[0] = Imodel[p];
    x[1] = Iobs[p];
    const float* mdp = metadata + (size_t)p * CMETA;
#pragma unroll
    for (int i = 0; i < CMETA; i++) x[2 + i] = mdp[i];

    float h[WD], h2[WD];
#pragma unroll
    for (int c = 0; c < WD; c++) {
        float a = bs0[c];
#pragma unroll
        for (int i = 0; i < CIN; i++) a = fmaf(x[i], WT0[c][i], a);
        h[c] = a;
    }
#pragma unroll 1
    for (int d = 0; d < DEPTH; d++) {
#pragma unroll
        for (int c = 0; c < WD; c++) {
            float a = bsd[d][c];
#pragma unroll
            for (int i = 0; i < WD; i++) a = fmaf(h[i], WT[d][c][i], a);
            h2[c] = fmaxf(a, 0.0f);
        }
#pragma unroll
        for (int c = 0; c < WD; c++) h[c] = h2[c];
    }

    const float m = mask_at(mask, fmt, p) ? 1.0f : 0.0f;

#pragma unroll
    for (int c = 0; c < WD; c++) {
        float v = m * h[c];
#pragma unroll
        for (int o = 16; o > 0; o >>= 1) v += __shfl_xor_sync(0xFFFFFFFFu, v, o);
        if ((tid & 31) == 0) atomicAdd(&g_img_sum[b][c], v);
    }
    {
        float v = m;
#pragma unroll
        for (int o = 16; o > 0; o >>= 1) v += __shfl_xor_sync(0xFFFFFFFFu, v, o);
        if ((tid & 31) == 0) atomicAdd(&g_img_cnt[b], v);
    }
}

// ---------------------------------------------------------------------------
// Kernel 3: main branch. P=2 points/thread; weights read as float4 (LDS.128)
// and each weight fetch feeds 8 FMAs (4 i-values x 2 points) -> ~8:1 FMA:LDS.
// ---------------------------------------------------------------------------
__global__ void __launch_bounds__(TPB, 1) k_main(
    const float* __restrict__ metadata, const void* __restrict__ mask,
    const float* __restrict__ W_lin_in, const float* __restrict__ b_lin_in,
    const float* __restrict__ W_mlp, const float* __restrict__ b_mlp,
    const float* __restrict__ W_out, const float* __restrict__ b_out,
    float* __restrict__ out)
{
    __shared__ __align__(16) float W0s[WD * 8];            // [c][i], i padded 6->8
    __shared__ __align__(16) float Ws[DEPTH * WD * WD];    // [d][c][i] transposed
    __shared__ float beff[WD];                             // b_lin + image_rep[b]
    __shared__ float bsd[DEPTH][WD];
    __shared__ __align__(16) float wouts[WD];
    __shared__ float bout_s;

    const int tid = threadIdx.x;
    const int p0 = blockIdx.x * PTSBLK;
    const int b = p0 / JK;                                 // PTSBLK divides JK

    for (int t = tid; t < WD * 8; t += TPB) {
        int c = t >> 3, i = t & 7;
        W0s[t] = (i < CMETA) ? W_lin_in[i * WD + c] : 0.0f;
    }
    for (int t = tid; t < DEPTH * WD * WD; t += TPB) {
        int d = t / (WD * WD); int r = t % (WD * WD); int i = r / WD, c = r % WD;
        Ws[(d * WD + c) * WD + i] = W_mlp[t];
    }
    if (tid < WD) {
        beff[tid] = b_lin_in[tid] + g_img_sum[b][tid] / g_img_cnt[b];
        wouts[tid] = W_out[tid];
    }
    for (int t = tid; t < DEPTH * WD; t += TPB) bsd[t / WD][t % WD] = b_mlp[t];
    if (tid == 0) bout_s = b_out[0];
    __syncthreads();

    const int fmt = g_fmt;
    const int p = p0 + tid;
    const int q = p + TPB;

    // inputs, padded to 8
    float x0[8], x1[8];
    {
        const float* m0 = metadata + (size_t)p * CMETA;
        const float* m1 = metadata + (size_t)q * CMETA;
#pragma unroll
        for (int i = 0; i < CMETA; i++) { x0[i] = m0[i]; x1[i] = m1[i]; }
        x0[6] = x0[7] = 0.0f; x1[6] = x1[7] = 0.0f;
    }

    float h0[WD], h1[WD], o0[WD], o1[WD];

    // input layer (beff = b_lin + image_rep folded)
#pragma unroll
    for (int c = 0; c < WD; c++) {
        float a0 = beff[c], a1 = a0;
        const float4* wr = (const float4*)&W0s[c * 8];
#pragma unroll
        for (int i4 = 0; i4 < 2; i4++) {
            float4 w = wr[i4];
            a0 = fmaf(x0[i4 * 4 + 0], w.x, a0);
            a0 = fmaf(x0[i4 * 4 + 1], w.y, a0);
            a0 = fmaf(x0[i4 * 4 + 2], w.z, a0);
            a0 = fmaf(x0[i4 * 4 + 3], w.w, a0);
            a1 = fmaf(x1[i4 * 4 + 0], w.x, a1);
            a1 = fmaf(x1[i4 * 4 + 1], w.y, a1);
            a1 = fmaf(x1[i4 * 4 + 2], w.z, a1);
            a1 = fmaf(x1[i4 * 4 + 3], w.w, a1);
        }
        h0[c] = a0; h1[c] = a1;
    }

    // hidden layers
#pragma unroll 1
    for (int d = 0; d < DEPTH; d++) {
        const float4* wl = (const float4*)&Ws[d * WD * WD];
#pragma unroll
        for (int c = 0; c < WD; c++) {
            float a0 = bsd[d][c], a1 = a0;
#pragma unroll
            for (int i4 = 0; i4 < 8; i4++) {
                float4 w = wl[c * 8 + i4];
                a0 = fmaf(h0[i4 * 4 + 0], w.x, a0);
                a0 = fmaf(h0[i4 * 4 + 1], w.y, a0);
                a0 = fmaf(h0[i4 * 4 + 2], w.z, a0);
                a0 = fmaf(h0[i4 * 4 + 3], w.w, a0);
                a1 = fmaf(h1[i4 * 4 + 0], w.x, a1);
                a1 = fmaf(h1[i4 * 4 + 1], w.y, a1);
                a1 = fmaf(h1[i4 * 4 + 2], w.z, a1);
                a1 = fmaf(h1[i4 * 4 + 3], w.w, a1);
            }
            o0[c] = fmaxf(a0, 0.0f);
            o1[c] = fmaxf(a1, 0.0f);
        }
#pragma unroll
        for (int c = 0; c < WD; c++) { h0[c] = o0[c]; h1[c] = o1[c]; }
    }

    // output layer
    float r0 = bout_s, r1 = bout_s;
    const float4* wo = (const float4*)wouts;
#pragma unroll
    for (int i4 = 0; i4 < 8; i4++) {
        float4 w = wo[i4];
        r0 = fmaf(h0[i4 * 4 + 0], w.x, r0);
        r0 = fmaf(h0[i4 * 4 + 1], w.y, r0);
        r0 = fmaf(h0[i4 * 4 + 2], w.z, r0);
        r0 = fmaf(h0[i4 * 4 + 3], w.w, r0);
        r1 = fmaf(h1[i4 * 4 + 0], w.x, r1);
        r1 = fmaf(h1[i4 * 4 + 1], w.y, r1);
        r1 = fmaf(h1[i4 * 4 + 2], w.z, r1);
        r1 = fmaf(h1[i4 * 4 + 3], w.w, r1);
    }

    out[p] = mask_at(mask, fmt, p) ? r0 : 0.0f;
    out[q] = mask_at(mask, fmt, q) ? r1 : 0.0f;
}

// ---------------------------------------------------------------------------
// Launch: select(+detect) -> image -> main (default stream, graph-capturable)
// ---------------------------------------------------------------------------
extern "C" void kernel_launch(void* const* d_in, const int* in_sizes, int n_in,
                              void* d_out, int out_size)
{
    const float* Imodel   = (const float*)d_in[0];
    const float* Iobs     = (const float*)d_in[1];
    const float* metadata = (const float*)d_in[2];
    const void*  mask     = d_in[3];
    // d_in[4] = sample_size (always 32)
    const float* W_img_in = (const float*)d_in[5];
    const float* b_img_in = (const float*)d_in[6];
    const float* W_img    = (const float*)d_in[7];
    const float* b_img    = (const float*)d_in[8];
    const float* W_lin_in = (const float*)d_in[9];
    const float* b_lin_in = (const float*)d_in[10];
    const float* W_mlp    = (const float*)d_in[11];
    const float* b_mlp    = (const float*)d_in[12];
    const float* W_out    = (const float*)d_in[13];
    const float* b_out    = (const float*)d_in[14];
    float* out = (float*)d_out;

    k_select<<<BB, JJ>>>(mask);
    k_image<<<BB * SS * 3, 128>>>(Imodel, Iobs, metadata, mask,
                                  W_img_in, b_img_in, W_img, b_img);
    k_main<<<NPTS / PTSBLK, TPB>>>(metadata, mask, W_lin_in, b_lin_in,
                                   W_mlp, b_mlp, W_out, b_out, out);
}